// round 14
// baseline (speedup 1.0000x reference)
#include <cuda_runtime.h>
#include <cuda_bf16.h>
#include <cstdint>

// Problem constants
#define B_ 128
#define T_ 2048
#define D_ 128
#define H_ 512
#define G_ 2048   // 4*H
#define K_ 640    // H + D
#define L_ 10

// Tiling: 4 batch groups x 32 column-tile CTAs (R6 shape — best known).
// Within a CTA: 8 warps = 4 k-chunks (160) x 2 n-halves (32).
#define MT 4
#define NT 32
#define NBLK (MT*NT)
#define THREADS 256

// Smem strides (bf16 elements)
#define WS_STR 648
#define AS_STR 648
#define XS_STR 136

// Smem byte offsets
#define OFF_WS 0
#define OFF_AS (64*WS_STR*2)            // 82944
#define OFF_GS (OFF_AS + 32*AS_STR*2)   // 124416 : 4 slabs of [32][68] fp32
#define OFF_CS (OFF_GS + 4*32*68*4)     // 159232 : fp32 cell [32][16]
#define OFF_BS (OFF_CS + 32*16*4)       // 161280 : fp32 bias [64]
#define OFF_X  (OFF_BS + 64*4)          // 161536 : x double buffer
#define XBUF   (32*XS_STR*2)            // 8704 per buffer
#define SMEM_BYTES (OFF_X + 2*XBUF)     // 178944

// Device-global scratch (all explicitly aligned — R2 lesson)
__device__ __align__(256) __nv_bfloat16 g_Wpk[G_][K_];
__device__ __align__(256) float         g_bpk[G_];
__device__ __align__(256) __nv_bfloat16 g_h[2][B_][H_];
__device__ __align__(256) __nv_bfloat16 g_xB[(size_t)B_*T_*D_];
__device__ __align__(256) unsigned      g_flag[MT*NT*32];   // per-CTA flags, 128B apart

__device__ __forceinline__ float tanhapx(float x){
    float y; asm("tanh.approx.f32 %0, %1;" : "=f"(y) : "f"(x)); return y;
}
__device__ __forceinline__ float sigm(float x){
    return fmaf(tanhapx(0.5f*x), 0.5f, 0.5f);
}

#define CPA16(dst, src) asm volatile("cp.async.cg.shared.global [%0], [%1], 16;" :: "r"(dst), "l"(src))

// ---------------- setup kernels ----------------
__global__ void xconv_kernel(const float* __restrict__ x){
    size_t i = (size_t)blockIdx.x*blockDim.x + threadIdx.x;
    float4 v = ((const float4*)x)[i];
    __nv_bfloat162* dst = (__nv_bfloat162*)g_xB;
    dst[2*i]   = __floats2bfloat162_rn(v.x, v.y);
    dst[2*i+1] = __floats2bfloat162_rn(v.z, v.w);
}

__global__ void pack_kernel(const float* __restrict__ W_ih,
                            const float* __restrict__ W_hh,
                            const float* __restrict__ b){
    int p = blockIdx.x;
    int j = p >> 2;
    int g = p & 3;
    int src = g*H_ + j;
    for (int k = threadIdx.x; k < K_; k += blockDim.x){
        float v = (k < H_) ? W_hh[src*H_ + k] : W_ih[src*D_ + (k - H_)];
        g_Wpk[p][k] = __float2bfloat16_rn(v);
    }
    if (threadIdx.x == 0) g_bpk[p] = b[src];
}

__global__ void init_kernel(){
    int i = blockIdx.x*blockDim.x + threadIdx.x;
    if (i < B_*H_) ((__nv_bfloat16*)g_h)[i] = __float2bfloat16(0.0f);
    if (i < MT*NT*32) g_flag[i] = 0u;
}

// ---------------- main persistent scan kernel ----------------
__global__ void __launch_bounds__(THREADS, 1) lstm_scan(){
    extern __shared__ char smc[];
    const uint32_t sb = (uint32_t)__cvta_generic_to_shared(smc);
    float* Gs = (float*)(smc + OFF_GS);
    float* cs = (float*)(smc + OFF_CS);
    float* bs = (float*)(smc + OFF_BS);

    const int tid = threadIdx.x;
    const int nb_ = blockIdx.x % NT;
    const int mb_ = blockIdx.x / NT;
    const int m0 = mb_ * 32;
    const int p0 = nb_ * 64;
    const int j0 = nb_ * 16;

    // Load weight slice once: 64 rows x 640 bf16 (80 float4 per row)
    {
        const float4* src = (const float4*)&g_Wpk[p0][0];
        for (int i = tid; i < 64*80; i += THREADS){
            int r = i/80, c = i%80;
            *(float4*)(smc + OFF_WS + r*WS_STR*2 + c*16) = __ldcg(src + (size_t)r*80 + c);
        }
    }
    if (tid < 64) bs[tid] = g_bpk[p0 + tid];
    for (int i = tid; i < 32*16; i += THREADS) cs[i] = 0.0f;
    __syncthreads();

    const int lane = tid & 31, warp = tid >> 5;
    const int grp = lane >> 2, tig = lane & 3;
    const int wk  = warp & 3;        // k-chunk (160 wide = 10 q-steps)
    const int wn2 = warp >> 2;       // n-half (32 cols)

    // ---- B fragments: load ONCE into registers for all T steps (R6-proven) ----
    uint32_t bf[10][2][4];
    {
        const int brow = ((lane >> 4) << 3) + (lane & 7);
        const int bcol8 = ((lane >> 3) & 1) * 8;
        #pragma unroll
        for (int q = 0; q < 10; ++q)
            #pragma unroll
            for (int nn = 0; nn < 2; ++nn){
                uint32_t addr = sb + OFF_WS +
                    (uint32_t)(((wn2*32 + nn*16 + brow)*WS_STR + wk*160 + q*16 + bcol8)*2);
                asm volatile("ldmatrix.sync.aligned.m8n8.x4.shared.b16 {%0,%1,%2,%3}, [%4];"
                    : "=r"(bf[q][nn][0]),"=r"(bf[q][nn][1]),"=r"(bf[q][nn][2]),"=r"(bf[q][nn][3])
                    : "r"(addr));
            }
    }

    // A-fragment (h region) and X-buffer per-lane base offsets
    uint32_t aBase[2], xOff[2];
    #pragma unroll
    for (int mh = 0; mh < 2; ++mh){
        aBase[mh] = sb + OFF_AS +
            (uint32_t)(((mh*16 + (lane & 15))*AS_STR + (lane >> 4)*8)*2);
        xOff[mh] = (uint32_t)(((mh*16 + (lane & 15))*XS_STR + (lane >> 4)*8)*2);
    }

    // This CTA's flag + the flag warp0's lane polls (lane l watches producer l)
    unsigned* myFlag = &g_flag[(mb_*NT + nb_)*32];
    const unsigned* poFlag = &g_flag[(mb_*NT + lane)*32];

    // Prologue: prefetch x(0) into X buffer 0 (512 segs, 2 per thread)
    {
        const __nv_bfloat16* xsrc = g_xB + ((size_t)m0*T_ + 0)*D_;
        #pragma unroll
        for (int i = 0; i < 2; ++i){
            int s = tid + i*THREADS;
            int r = s >> 4, c = s & 15;
            CPA16(sb + OFF_X + (uint32_t)(r*XS_STR*2 + c*16),
                  xsrc + (size_t)r*T_*D_ + c*8);
        }
        asm volatile("cp.async.commit_group;");
    }

    for (int t = 0; t < T_; ++t){
        // ---- h-part bulk load via cp.async: 32 rows x 512 bf16 ----
        {
            const __nv_bfloat16* hsrc = &g_h[t & 1][m0][0];
            #pragma unroll
            for (int i = 0; i < 8; ++i){
                int s = tid + i*THREADS;
                int r = s >> 6, c = s & 63;
                CPA16(sb + OFF_AS + (uint32_t)(r*AS_STR*2 + c*16), hsrc + r*H_ + c*8);
            }
            asm volatile("cp.async.commit_group;");
            asm volatile("cp.async.wait_group 0;");   // drains h(t) + x(t) prefetch
        }
        __syncthreads();

        // ---- MMA: m32 x n32 x k160 per warp; A frags double-buffered ----
        // k cols [wk*160, wk*160+160): cols >= 512 come from the X buffer.
        float acc[2][4][4] = {};
        {
            const uint32_t xcur = sb + OFF_X + (uint32_t)((t & 1)*XBUF);
            uint32_t a[2][2][4];
            #define LDA(buf, qq) do {                                            \
                int col0 = wk*160 + (qq)*16;                                     \
                _Pragma("unroll")                                                \
                for (int mh = 0; mh < 2; ++mh){                                  \
                    uint32_t addr = (col0 < 512)                                 \
                        ? (aBase[mh] + (uint32_t)(col0*2))                       \
                        : (xcur + xOff[mh] + (uint32_t)((col0 - 512)*2));        \
                    asm volatile("ldmatrix.sync.aligned.m8n8.x4.shared.b16 "     \
                        "{%0,%1,%2,%3}, [%4];"                                   \
                        : "=r"((buf)[mh][0]),"=r"((buf)[mh][1]),                 \
                          "=r"((buf)[mh][2]),"=r"((buf)[mh][3])                  \
                        : "r"(addr));                                            \
                }                                                                \
            } while(0)
            LDA(a[0], 0);
            #pragma unroll
            for (int q = 0; q < 10; ++q){
                const int cur = q & 1, nxt = cur ^ 1;
                if (q < 9) LDA(a[nxt], q + 1);
                #pragma unroll
                for (int mh = 0; mh < 2; ++mh)
                    #pragma unroll
                    for (int nn = 0; nn < 2; ++nn){
                        float* A0 = acc[mh][2*nn];
                        float* A1 = acc[mh][2*nn + 1];
                        asm("mma.sync.aligned.m16n8k16.row.col.f32.bf16.bf16.f32 "
                            "{%0,%1,%2,%3}, {%4,%5,%6,%7}, {%8,%9}, {%0,%1,%2,%3};"
                            : "+f"(A0[0]),"+f"(A0[1]),"+f"(A0[2]),"+f"(A0[3])
                            : "r"(a[cur][mh][0]),"r"(a[cur][mh][1]),
                              "r"(a[cur][mh][2]),"r"(a[cur][mh][3]),
                              "r"(bf[q][nn][0]),"r"(bf[q][nn][1]));
                        asm("mma.sync.aligned.m16n8k16.row.col.f32.bf16.bf16.f32 "
                            "{%0,%1,%2,%3}, {%4,%5,%6,%7}, {%8,%9}, {%0,%1,%2,%3};"
                            : "+f"(A1[0]),"+f"(A1[1]),"+f"(A1[2]),"+f"(A1[3])
                            : "r"(a[cur][mh][0]),"r"(a[cur][mh][1]),
                              "r"(a[cur][mh][2]),"r"(a[cur][mh][3]),
                              "r"(bf[q][nn][2]),"r"(bf[q][nn][3]));
                    }
            }
            #undef LDA
        }

        // ---- scatter partial gates to slab[wk] ----
        {
            float* Gw = Gs + wk*(32*68);
            #pragma unroll
            for (int mh = 0; mh < 2; ++mh){
                int r0 = (mh*16 + grp)*68, r1 = r0 + 8*68;
                #pragma unroll
                for (int nn = 0; nn < 2; ++nn)
                    #pragma unroll
                    for (int hi = 0; hi < 2; ++hi){
                        int c = wn2*32 + nn*16 + hi*8 + 2*tig;
                        float* A = acc[mh][2*nn + hi];
                        *(float2*)&Gw[r0 + c] = make_float2(A[0], A[1]);
                        *(float2*)&Gw[r1 + c] = make_float2(A[2], A[3]);
                    }
            }
        }
        __syncthreads();

        // ---- reduce 4 k-partials + LSTM cell update (2 pairs per thread) ----
        const int wbuf = (t + 1) & 1;
        {
            int b  = tid >> 3;
            int jp = tid & 7;               // jj pair: 2*jp, 2*jp+1
            float4 s0 = *(const float4*)&bs[8*jp];
            float4 s1 = *(const float4*)&bs[8*jp + 4];
            #pragma unroll
            for (int w = 0; w < 4; ++w){
                const float* base = &Gs[w*(32*68) + b*68 + 8*jp];
                float4 v0 = *(const float4*)(base);
                float4 v1 = *(const float4*)(base + 4);
                s0.x += v0.x; s0.y += v0.y; s0.z += v0.z; s0.w += v0.w;
                s1.x += v1.x; s1.y += v1.y; s1.z += v1.z; s1.w += v1.w;
            }
            float c0 = cs[b*16 + 2*jp], c1 = cs[b*16 + 2*jp + 1];
            float cn0 = sigm(s0.y)*c0 + sigm(s0.x)*tanhapx(s0.z);
            float cn1 = sigm(s1.y)*c1 + sigm(s1.x)*tanhapx(s1.z);
            float hn0 = sigm(s0.w)*tanhapx(cn0);
            float hn1 = sigm(s1.w)*tanhapx(cn1);
            cs[b*16 + 2*jp]     = cn0;
            cs[b*16 + 2*jp + 1] = cn1;
            __nv_bfloat162 hp = __floats2bfloat162_rn(hn0, hn1);
            unsigned hv = *(unsigned*)&hp;
            __nv_bfloat16* dst = &g_h[wbuf][m0 + b][j0 + 2*jp];
            asm volatile("st.global.cg.u32 [%0], %1;" :: "l"(dst), "r"(hv));
        }
        __syncthreads();

        // ---- prefetch x(t+1) into the other X buffer (overlaps publish/poll) ----
        if (t + 1 < T_){
            const __nv_bfloat16* xsrc = g_xB + ((size_t)m0*T_ + (t + 1))*D_;
            const uint32_t xnxt = sb + OFF_X + (uint32_t)(((t + 1) & 1)*XBUF);
            #pragma unroll
            for (int i = 0; i < 2; ++i){
                int s = tid + i*THREADS;
                int r = s >> 4, c = s & 15;
                CPA16(xnxt + (uint32_t)(r*XS_STR*2 + c*16),
                      xsrc + (size_t)r*T_*D_ + c*8);
            }
            asm volatile("cp.async.commit_group;");
        }

        // ---- flag barrier: one release-store, 32 parallel acquire-polls ----
        if (tid == 0){
            asm volatile("st.global.release.gpu.u32 [%0], %1;"
                         :: "l"(myFlag), "r"((unsigned)(t + 1)));
        }
        if (warp == 0){
            unsigned v;
            do {
                asm volatile("ld.global.acquire.gpu.u32 %0, [%1];" : "=r"(v) : "l"(poFlag));
            } while (v < (unsigned)(t + 1));
        }
        __syncthreads();
    }
}

// ---------------- output head: logits + softmax ----------------
__global__ void out_kernel(const float* __restrict__ W_out, float* __restrict__ out){
    int b = blockIdx.x;
    int lane = threadIdx.x;
    float acc[L_];
    #pragma unroll
    for (int l = 0; l < L_; ++l) acc[l] = 0.0f;
    for (int k = lane; k < H_; k += 32){
        float hv = __bfloat162float(g_h[0][b][k]);   // T even -> final h in buffer 0
        #pragma unroll
        for (int l = 0; l < L_; ++l) acc[l] += hv * __ldg(&W_out[l*H_ + k]);
    }
    #pragma unroll
    for (int l = 0; l < L_; ++l){
        #pragma unroll
        for (int o = 16; o; o >>= 1) acc[l] += __shfl_xor_sync(0xffffffffu, acc[l], o);
    }
    if (lane == 0){
        float mx = acc[0];
        #pragma unroll
        for (int l = 1; l < L_; ++l) mx = fmaxf(mx, acc[l]);
        float s = 0.0f;
        #pragma unroll
        for (int l = 0; l < L_; ++l){ acc[l] = expf(acc[l] - mx); s += acc[l]; }
        float inv = 1.0f / s;
        #pragma unroll
        for (int l = 0; l < L_; ++l) out[b*L_ + l] = acc[l] * inv;
    }
}

// ---------------- launch ----------------
extern "C" void kernel_launch(void* const* d_in, const int* in_sizes, int n_in,
                              void* d_out, int out_size){
    const float* x     = (const float*)d_in[0];
    const float* W_ih  = (const float*)d_in[1];
    const float* W_hh  = (const float*)d_in[2];
    const float* b     = (const float*)d_in[3];
    const float* W_out = (const float*)d_in[4];

    cudaFuncSetAttribute(lstm_scan, cudaFuncAttributeMaxDynamicSharedMemorySize, SMEM_BYTES);

    xconv_kernel<<<(B_*T_*D_/4)/256, 256>>>(x);
    pack_kernel<<<G_, 256>>>(W_ih, W_hh, b);
    init_kernel<<<256, 256>>>();
    lstm_scan<<<NBLK, THREADS, SMEM_BYTES>>>();
    out_kernel<<<B_, 32>>>(W_out, (float*)d_out);
}

// round 15
// speedup vs baseline: 1.2569x; 1.2569x over previous
#include <cuda_runtime.h>
#include <cuda_bf16.h>
#include <cstdint>

// Problem constants
#define B_ 128
#define T_ 2048
#define D_ 128
#define H_ 512
#define G_ 2048   // 4*H
#define K_ 640    // H + D
#define L_ 10

// Tiling: 4 batch groups x 32 column-tile CTAs (R6 shape — best known).
// Within a CTA: 8 warps = 4 k-chunks (160) x 2 n-halves (32).
#define MT 4
#define NT 32
#define NBLK (MT*NT)
#define THREADS 256

// Smem strides (bf16 elements)
#define WS_STR 648
#define AS_STR 648

// Smem byte offsets
#define OFF_WS 0
#define OFF_AS (64*WS_STR*2)            // 82944
#define OFF_GS (OFF_AS + 32*AS_STR*2)   // 124416 : 4 slabs of [32][68] fp32
#define OFF_CS (OFF_GS + 4*32*68*4)     // 159232 : fp32 cell [32][16]
#define OFF_BS (OFF_CS + 32*16*4)       // 161280 : fp32 bias [64]
#define SMEM_BYTES (OFF_BS + 64*4)      // 161536

// Device-global scratch (all explicitly aligned — R2 lesson)
__device__ __align__(256) __nv_bfloat16 g_Wpk[G_][K_];
__device__ __align__(256) float         g_bpk[G_];
__device__ __align__(256) __nv_bfloat16 g_h[2][B_][H_];
__device__ __align__(256) __nv_bfloat16 g_xB[(size_t)B_*T_*D_];
__device__ __align__(256) unsigned      g_flag[MT*NT*32];   // per-CTA flags, 128B apart

__device__ __forceinline__ float tanhapx(float x){
    float y; asm("tanh.approx.f32 %0, %1;" : "=f"(y) : "f"(x)); return y;
}
__device__ __forceinline__ float sigm(float x){
    return fmaf(tanhapx(0.5f*x), 0.5f, 0.5f);
}

#define CPA16(dst, src) asm volatile("cp.async.cg.shared.global [%0], [%1], 16;" :: "r"(dst), "l"(src))

// ---------------- setup kernels ----------------
__global__ void xconv_kernel(const float* __restrict__ x){
    size_t i = (size_t)blockIdx.x*blockDim.x + threadIdx.x;
    float4 v = ((const float4*)x)[i];
    __nv_bfloat162* dst = (__nv_bfloat162*)g_xB;
    dst[2*i]   = __floats2bfloat162_rn(v.x, v.y);
    dst[2*i+1] = __floats2bfloat162_rn(v.z, v.w);
}

__global__ void pack_kernel(const float* __restrict__ W_ih,
                            const float* __restrict__ W_hh,
                            const float* __restrict__ b){
    int p = blockIdx.x;
    int j = p >> 2;
    int g = p & 3;
    int src = g*H_ + j;
    for (int k = threadIdx.x; k < K_; k += blockDim.x){
        float v = (k < H_) ? W_hh[src*H_ + k] : W_ih[src*D_ + (k - H_)];
        g_Wpk[p][k] = __float2bfloat16_rn(v);
    }
    if (threadIdx.x == 0) g_bpk[p] = b[src];
}

__global__ void init_kernel(){
    int i = blockIdx.x*blockDim.x + threadIdx.x;
    if (i < B_*H_) ((__nv_bfloat16*)g_h)[i] = __float2bfloat16(0.0f);
    if (i < MT*NT*32) g_flag[i] = 0u;
}

// ---------------- main persistent scan kernel ----------------
__global__ void __launch_bounds__(THREADS, 1) lstm_scan(){
    extern __shared__ char smc[];
    const uint32_t sb = (uint32_t)__cvta_generic_to_shared(smc);
    float* Gs = (float*)(smc + OFF_GS);
    float* cs = (float*)(smc + OFF_CS);
    float* bs = (float*)(smc + OFF_BS);

    const int tid = threadIdx.x;
    const int nb_ = blockIdx.x % NT;
    const int mb_ = blockIdx.x / NT;
    const int m0 = mb_ * 32;
    const int p0 = nb_ * 64;
    const int j0 = nb_ * 16;

    // Load weight slice once: 64 rows x 640 bf16 (80 float4 per row)
    {
        const float4* src = (const float4*)&g_Wpk[p0][0];
        for (int i = tid; i < 64*80; i += THREADS){
            int r = i/80, c = i%80;
            *(float4*)(smc + OFF_WS + r*WS_STR*2 + c*16) = __ldcg(src + (size_t)r*80 + c);
        }
    }
    if (tid < 64) bs[tid] = g_bpk[p0 + tid];
    for (int i = tid; i < 32*16; i += THREADS) cs[i] = 0.0f;
    __syncthreads();

    const int lane = tid & 31, warp = tid >> 5;
    const int grp = lane >> 2, tig = lane & 3;
    const int wk  = warp & 3;        // k-chunk (160 wide = 10 q-steps)
    const int wn2 = warp >> 2;       // n-half (32 cols)

    // ---- B fragments: load ONCE into registers for all T steps (R6-proven) ----
    uint32_t bf[10][2][4];
    {
        const int brow = ((lane >> 4) << 3) + (lane & 7);
        const int bcol8 = ((lane >> 3) & 1) * 8;
        #pragma unroll
        for (int q = 0; q < 10; ++q)
            #pragma unroll
            for (int nn = 0; nn < 2; ++nn){
                uint32_t addr = sb + OFF_WS +
                    (uint32_t)(((wn2*32 + nn*16 + brow)*WS_STR + wk*160 + q*16 + bcol8)*2);
                asm volatile("ldmatrix.sync.aligned.m8n8.x4.shared.b16 {%0,%1,%2,%3}, [%4];"
                    : "=r"(bf[q][nn][0]),"=r"(bf[q][nn][1]),"=r"(bf[q][nn][2]),"=r"(bf[q][nn][3])
                    : "r"(addr));
            }
    }

    // A-fragment ldmatrix base addresses
    uint32_t aBase[2];
    #pragma unroll
    for (int mh = 0; mh < 2; ++mh)
        aBase[mh] = sb + OFF_AS +
            (uint32_t)(((mh*16 + (lane & 15))*AS_STR + (lane >> 4)*8)*2);

    // This CTA's flag + the flag warp0's lane polls (lane l watches producer l)
    unsigned* myFlag = &g_flag[(mb_*NT + nb_)*32];
    const unsigned* poFlag = &g_flag[(mb_*NT + lane)*32];

    for (int t = 0; t < T_; ++t){
        // ---- 2-stripe A load. Stripe g covers, for every k-chunk, its
        //      cols [chunk*160 + g*80, +80). 1280 16B-segs per stripe. ----
        const __nv_bfloat16* hsrc = &g_h[t & 1][m0][0];
        const __nv_bfloat16* xsrc = g_xB + ((size_t)m0*T_ + t)*D_;
        #pragma unroll
        for (int g = 0; g < 2; ++g){
            #pragma unroll
            for (int i = 0; i < 5; ++i){
                int seg = tid + i*THREADS;          // 0..1279
                int r = seg / 40;
                int j = seg - r*40;                 // 0..39
                int chunk = j >> 3 >= 0 ? j/10 : 0; // 0..3
                int cseg  = j - chunk*10;           // 0..9
                int col8  = chunk*20 + g*10 + cseg; // 8-col units within row
                int col   = col8*8;
                const __nv_bfloat16* src = (col < H_)
                    ? (hsrc + r*H_ + col)
                    : (xsrc + (size_t)r*T_*D_ + (col - H_));
                CPA16(sb + OFF_AS + (uint32_t)(r*AS_STR*2 + col8*16), src);
            }
            asm volatile("cp.async.commit_group;");
        }

        // ---- MMA with intra-step pipeline: half 0 runs while stripe 1 lands ----
        float acc[2][4][4] = {};
        #pragma unroll
        for (int g = 0; g < 2; ++g){
            if (g == 0) asm volatile("cp.async.wait_group 1;");
            else        asm volatile("cp.async.wait_group 0;");
            __syncthreads();

            const uint32_t kbase = (uint32_t)(wk*320 + g*160);   // byte offset
            uint32_t a[2][2][4];
            #pragma unroll
            for (int mh = 0; mh < 2; ++mh)
                asm volatile("ldmatrix.sync.aligned.m8n8.x4.shared.b16 {%0,%1,%2,%3}, [%4];"
                    : "=r"(a[0][mh][0]),"=r"(a[0][mh][1]),"=r"(a[0][mh][2]),"=r"(a[0][mh][3])
                    : "r"(aBase[mh] + kbase));
            #pragma unroll
            for (int qq = 0; qq < 5; ++qq){
                const int q = g*5 + qq;
                const int cur = qq & 1, nxt = cur ^ 1;
                if (qq < 4){
                    #pragma unroll
                    for (int mh = 0; mh < 2; ++mh)
                        asm volatile("ldmatrix.sync.aligned.m8n8.x4.shared.b16 {%0,%1,%2,%3}, [%4];"
                            : "=r"(a[nxt][mh][0]),"=r"(a[nxt][mh][1]),
                              "=r"(a[nxt][mh][2]),"=r"(a[nxt][mh][3])
                            : "r"(aBase[mh] + kbase + (qq+1)*32));
                }
                #pragma unroll
                for (int mh = 0; mh < 2; ++mh)
                    #pragma unroll
                    for (int nn = 0; nn < 2; ++nn){
                        float* A0 = acc[mh][2*nn];
                        float* A1 = acc[mh][2*nn + 1];
                        asm("mma.sync.aligned.m16n8k16.row.col.f32.bf16.bf16.f32 "
                            "{%0,%1,%2,%3}, {%4,%5,%6,%7}, {%8,%9}, {%0,%1,%2,%3};"
                            : "+f"(A0[0]),"+f"(A0[1]),"+f"(A0[2]),"+f"(A0[3])
                            : "r"(a[cur][mh][0]),"r"(a[cur][mh][1]),
                              "r"(a[cur][mh][2]),"r"(a[cur][mh][3]),
                              "r"(bf[q][nn][0]),"r"(bf[q][nn][1]));
                        asm("mma.sync.aligned.m16n8k16.row.col.f32.bf16.bf16.f32 "
                            "{%0,%1,%2,%3}, {%4,%5,%6,%7}, {%8,%9}, {%0,%1,%2,%3};"
                            : "+f"(A1[0]),"+f"(A1[1]),"+f"(A1[2]),"+f"(A1[3])
                            : "r"(a[cur][mh][0]),"r"(a[cur][mh][1]),
                              "r"(a[cur][mh][2]),"r"(a[cur][mh][3]),
                              "r"(bf[q][nn][2]),"r"(bf[q][nn][3]));
                    }
            }
        }

        // ---- scatter partial gates to slab[wk] ----
        {
            float* Gw = Gs + wk*(32*68);
            #pragma unroll
            for (int mh = 0; mh < 2; ++mh){
                int r0 = (mh*16 + grp)*68, r1 = r0 + 8*68;
                #pragma unroll
                for (int nn = 0; nn < 2; ++nn)
                    #pragma unroll
                    for (int hi = 0; hi < 2; ++hi){
                        int c = wn2*32 + nn*16 + hi*8 + 2*tig;
                        float* A = acc[mh][2*nn + hi];
                        *(float2*)&Gw[r0 + c] = make_float2(A[0], A[1]);
                        *(float2*)&Gw[r1 + c] = make_float2(A[2], A[3]);
                    }
            }
        }
        __syncthreads();

        // ---- reduce 4 k-partials + LSTM cell update (2 pairs per thread) ----
        const int wbuf = (t + 1) & 1;
        {
            int b  = tid >> 3;
            int jp = tid & 7;               // jj pair: 2*jp, 2*jp+1
            float4 s0 = *(const float4*)&bs[8*jp];
            float4 s1 = *(const float4*)&bs[8*jp + 4];
            #pragma unroll
            for (int w = 0; w < 4; ++w){
                const float* base = &Gs[w*(32*68) + b*68 + 8*jp];
                float4 v0 = *(const float4*)(base);
                float4 v1 = *(const float4*)(base + 4);
                s0.x += v0.x; s0.y += v0.y; s0.z += v0.z; s0.w += v0.w;
                s1.x += v1.x; s1.y += v1.y; s1.z += v1.z; s1.w += v1.w;
            }
            float c0 = cs[b*16 + 2*jp], c1 = cs[b*16 + 2*jp + 1];
            float cn0 = sigm(s0.y)*c0 + sigm(s0.x)*tanhapx(s0.z);
            float cn1 = sigm(s1.y)*c1 + sigm(s1.x)*tanhapx(s1.z);
            float hn0 = sigm(s0.w)*tanhapx(cn0);
            float hn1 = sigm(s1.w)*tanhapx(cn1);
            cs[b*16 + 2*jp]     = cn0;
            cs[b*16 + 2*jp + 1] = cn1;
            __nv_bfloat162 hp = __floats2bfloat162_rn(hn0, hn1);
            unsigned hv = *(unsigned*)&hp;
            __nv_bfloat16* dst = &g_h[wbuf][m0 + b][j0 + 2*jp];
            asm volatile("st.global.cg.u32 [%0], %1;" :: "l"(dst), "r"(hv));
        }
        __syncthreads();

        // ---- flag barrier: one release-store, 32 parallel acquire-polls ----
        if (tid == 0){
            asm volatile("st.global.release.gpu.u32 [%0], %1;"
                         :: "l"(myFlag), "r"((unsigned)(t + 1)));
        }
        if (warp == 0){
            unsigned v;
            do {
                asm volatile("ld.global.acquire.gpu.u32 %0, [%1];" : "=r"(v) : "l"(poFlag));
            } while (v < (unsigned)(t + 1));
        }
        __syncthreads();
    }
}

// ---------------- output head: logits + softmax ----------------
__global__ void out_kernel(const float* __restrict__ W_out, float* __restrict__ out){
    int b = blockIdx.x;
    int lane = threadIdx.x;
    float acc[L_];
    #pragma unroll
    for (int l = 0; l < L_; ++l) acc[l] = 0.0f;
    for (int k = lane; k < H_; k += 32){
        float hv = __bfloat162float(g_h[0][b][k]);   // T even -> final h in buffer 0
        #pragma unroll
        for (int l = 0; l < L_; ++l) acc[l] += hv * __ldg(&W_out[l*H_ + k]);
    }
    #pragma unroll
    for (int l = 0; l < L_; ++l){
        #pragma unroll
        for (int o = 16; o; o >>= 1) acc[l] += __shfl_xor_sync(0xffffffffu, acc[l], o);
    }
    if (lane == 0){
        float mx = acc[0];
        #pragma unroll
        for (int l = 1; l < L_; ++l) mx = fmaxf(mx, acc[l]);
        float s = 0.0f;
        #pragma unroll
        for (int l = 0; l < L_; ++l){ acc[l] = expf(acc[l] - mx); s += acc[l]; }
        float inv = 1.0f / s;
        #pragma unroll
        for (int l = 0; l < L_; ++l) out[b*L_ + l] = acc[l] * inv;
    }
}

// ---------------- launch ----------------
extern "C" void kernel_launch(void* const* d_in, const int* in_sizes, int n_in,
                              void* d_out, int out_size){
    const float* x     = (const float*)d_in[0];
    const float* W_ih  = (const float*)d_in[1];
    const float* W_hh  = (const float*)d_in[2];
    const float* b     = (const float*)d_in[3];
    const float* W_out = (const float*)d_in[4];

    cudaFuncSetAttribute(lstm_scan, cudaFuncAttributeMaxDynamicSharedMemorySize, SMEM_BYTES);

    xconv_kernel<<<(B_*T_*D_/4)/256, 256>>>(x);
    pack_kernel<<<G_, 256>>>(W_ih, W_hh, b);
    init_kernel<<<256, 256>>>();
    lstm_scan<<<NBLK, THREADS, SMEM_BYTES>>>();
    out_kernel<<<B_, 32>>>(W_out, (float*)d_out);
}